// round 11
// baseline (speedup 1.0000x reference)
#include <cuda_runtime.h>
#include <cuda_bf16.h>
#include <math.h>
#include <stdint.h>

// ---------------------------------------------------------------------------
// MambaDecoder: B=1, L=1024, D=1024, NL=4, DI=2048, N=16, DTR=64, K=4
// Round 7: chunked parallel selective scan (3 passes, full-chip) replacing
// the 64-warp serial scan. GEMMs remain split-bf16 HMMA (R6).
// ---------------------------------------------------------------------------

#define LSEQ 1024
#define DMODEL 1024
#define DI 2048
#define NSTATE 16
#define DTR 64
#define NL 4
#define NCH 16                 // scan chunks
#define CHT 64                 // timesteps per chunk

typedef __nv_bfloat16 bf16;

// ------------------------------------------------------------- PTX helpers --
__device__ __forceinline__ uint32_t smem_u32(const void* p) {
    uint32_t a;
    asm("{ .reg .u64 t; cvta.to.shared.u64 t, %1; cvt.u32.u64 %0, t; }"
        : "=r"(a) : "l"(p));
    return a;
}
__device__ __forceinline__ void cp_async16(uint32_t dst, const void* src) {
    asm volatile("cp.async.cg.shared.global [%0], [%1], 16;"
                 :: "r"(dst), "l"(src));
}
#define CP_COMMIT() asm volatile("cp.async.commit_group;" ::: "memory")
#define CP_WAIT1()  asm volatile("cp.async.wait_group 1;" ::: "memory")
#define CP_WAIT0()  asm volatile("cp.async.wait_group 0;" ::: "memory")

__device__ __forceinline__ void ldmx4(uint32_t* r, uint32_t a) {
    asm volatile("ldmatrix.sync.aligned.m8n8.x4.shared.b16 {%0,%1,%2,%3}, [%4];"
                 : "=r"(r[0]), "=r"(r[1]), "=r"(r[2]), "=r"(r[3]) : "r"(a));
}
__device__ __forceinline__ void mma16816(float* d, const uint32_t* a,
                                         uint32_t b0, uint32_t b1) {
    asm volatile(
        "mma.sync.aligned.m16n8k16.row.col.f32.bf16.bf16.f32 "
        "{%0,%1,%2,%3}, {%4,%5,%6,%7}, {%8,%9}, {%0,%1,%2,%3};"
        : "+f"(d[0]), "+f"(d[1]), "+f"(d[2]), "+f"(d[3])
        : "r"(a[0]), "r"(a[1]), "r"(a[2]), "r"(a[3]), "r"(b0), "r"(b1));
}

// ------------------------------------------------------------------ scratch --
__device__ float g_xz[LSEQ * 2 * DI];      // 16 MB
__device__ float g_uc[LSEQ * DI];          // 8 MB
__device__ float g_xdbl[LSEQ * 96];        // 0.4 MB
__device__ float g_delta[LSEQ * DI];       // 8 MB
__device__ float g_A[DI * NSTATE];
__device__ int   g_flag;
// chunked-scan scratch
__device__ float g_S[LSEQ * DI];           // 8 MB  cumulative delta (in-chunk)
__device__ float g_yloc[LSEQ * DI];        // 8 MB  local scan output
__device__ float g_hend[NCH * DI * NSTATE];// 2 MB  chunk-final local h
__device__ float g_hin[NCH * DI * NSTATE]; // 2 MB  chunk input state
__device__ float g_chsum[NCH * DI];        // 128 KB chunk delta sums
// split-bf16 operands
__device__ bf16 g_xnh[LSEQ * DMODEL];
__device__ bf16 g_xnl[LSEQ * DMODEL];
__device__ bf16 g_ygh[LSEQ * DI];
__device__ bf16 g_ygl[LSEQ * DI];
__device__ bf16 g_wih[2 * DI * DMODEL];    // in_w hi  (4096x1024)
__device__ bf16 g_wil[2 * DI * DMODEL];    // in_w lo
__device__ bf16 g_woh[DMODEL * DI];        // out_w hi (1024x2048)
__device__ bf16 g_wol[DMODEL * DI];        // out_w lo

__device__ __forceinline__ void split_bf16(float v, bf16& h, bf16& l) {
    h = __float2bfloat16(v);
    l = __float2bfloat16(v - __bfloat162float(h));
}

// ------------------------------------------------------------------ convert --
__global__ void cvt_kernel(const float* __restrict__ src,
                           bf16* __restrict__ hi, bf16* __restrict__ lo)
{
    int i = blockIdx.x * 256 + threadIdx.x;
    bf16 h, l;
    split_bf16(src[i], h, l);
    hi[i] = h; lo[i] = l;
}

// ---------------------------------------------------------------- rmsnorm --
__global__ void rmsnorm_kernel(const float* __restrict__ x,
                               const float* __restrict__ w,
                               bf16* __restrict__ oh, bf16* __restrict__ ol)
{
    int l = blockIdx.x;
    int t = threadIdx.x;            // 256 threads, 4 floats each
    const float4* xr = (const float4*)(x + l * DMODEL);
    float4 v = xr[t];
    float ss = v.x*v.x + v.y*v.y + v.z*v.z + v.w*v.w;
#pragma unroll
    for (int o = 16; o > 0; o >>= 1) ss += __shfl_xor_sync(0xffffffffu, ss, o);
    __shared__ float sred[8];
    if ((t & 31) == 0) sred[t >> 5] = ss;
    __syncthreads();
    float tot = 0.f;
#pragma unroll
    for (int i = 0; i < 8; i++) tot += sred[i];
    float rs = rsqrtf(tot * (1.0f / DMODEL) + 1e-5f);
    float4 wv = ((const float4*)w)[t];
    float o0 = v.x*rs*wv.x, o1 = v.y*rs*wv.y, o2 = v.z*rs*wv.z, o3 = v.w*rs*wv.w;
    size_t base = (size_t)l * DMODEL + t * 4;
    bf16 h, lo_;
    split_bf16(o0, h, lo_); oh[base+0] = h; ol[base+0] = lo_;
    split_bf16(o1, h, lo_); oh[base+1] = h; ol[base+1] = lo_;
    split_bf16(o2, h, lo_); oh[base+2] = h; ol[base+2] = lo_;
    split_bf16(o3, h, lo_); oh[base+3] = h; ol[base+3] = lo_;
}

// ------------------------------------------------- split-bf16 HMMA GEMM ----
// C[.,ldc] (+)= (Ah+Al)[M,K] * (Bh+Bl)[N,K]^T  (drop Al*Bl)
#define TPAD 40
#define TILE_E (128 * TPAD)
#define HG_SMEM (2 * 4 * TILE_E * 2)    // 81920 bytes

__device__ __forceinline__ void load_stage(
    bf16* s0, bf16* s1, bf16* s2, bf16* s3,
    const bf16* __restrict__ Ah, const bf16* __restrict__ Al,
    const bf16* __restrict__ Bh, const bf16* __restrict__ Bl,
    int bm, int bn, int K, int k0, int tid)
{
#pragma unroll
    for (int i = 0; i < 2; i++) {
        int j = tid + i * 256;          // 0..511
        int row = j >> 2, seg = j & 3;
        int off = row * TPAD + seg * 8;
        size_t ga = (size_t)(bm + row) * K + k0 + seg * 8;
        size_t gb = (size_t)(bn + row) * K + k0 + seg * 8;
        cp_async16(smem_u32(s0 + off), Ah + ga);
        cp_async16(smem_u32(s1 + off), Al + ga);
        cp_async16(smem_u32(s2 + off), Bh + gb);
        cp_async16(smem_u32(s3 + off), Bl + gb);
    }
}

template<bool ACC>
__global__ void __launch_bounds__(256, 2) hmma_gemm(
    const bf16* __restrict__ Ah, const bf16* __restrict__ Al,
    const bf16* __restrict__ Bh, const bf16* __restrict__ Bl,
    float* __restrict__ C, int ldc, int K)
{
    extern __shared__ __align__(16) bf16 sm[];
    const int tid = threadIdx.x;
    const int lane = tid & 31;
    const int wid = tid >> 5;
    const int wm = wid & 3;
    const int wn = wid >> 2;
    const int bm = blockIdx.y * 128;
    const int bn = blockIdx.x * 128;

    float acc[2][8][4];
#pragma unroll
    for (int i = 0; i < 2; i++)
#pragma unroll
        for (int j = 0; j < 8; j++)
#pragma unroll
            for (int k = 0; k < 4; k++) acc[i][j][k] = 0.f;

    const int nch = K >> 5;
    load_stage(sm, sm + TILE_E, sm + 2*TILE_E, sm + 3*TILE_E,
               Ah, Al, Bh, Bl, bm, bn, K, 0, tid);
    CP_COMMIT();

    for (int c = 0; c < nch; c++) {
        if (c + 1 < nch) {
            bf16* st = sm + ((c + 1) & 1) * 4 * TILE_E;
            load_stage(st, st + TILE_E, st + 2*TILE_E, st + 3*TILE_E,
                       Ah, Al, Bh, Bl, bm, bn, K, (c + 1) << 5, tid);
            CP_COMMIT();
            CP_WAIT1();
        } else {
            CP_WAIT0();
        }
        __syncthreads();

        bf16* SA_h = sm + (c & 1) * 4 * TILE_E;
        bf16* SA_l = SA_h + TILE_E;
        bf16* SB_h = SA_h + 2 * TILE_E;
        bf16* SB_l = SA_h + 3 * TILE_E;

#pragma unroll
        for (int ks = 0; ks < 32; ks += 16) {
            uint32_t ah[2][4], al[2][4];
#pragma unroll
            for (int ma = 0; ma < 2; ma++) {
                int r = wm * 32 + ma * 16 + (lane & 15);
                int cc = ks + (lane >> 4) * 8;
                ldmx4(ah[ma], smem_u32(SA_h + r * TPAD + cc));
                ldmx4(al[ma], smem_u32(SA_l + r * TPAD + cc));
            }
#pragma unroll
            for (int nb2 = 0; nb2 < 4; nb2++) {
                uint32_t bh[4], bl[4];
                int r = wn * 64 + nb2 * 16 + (lane & 15);
                int cc = ks + (lane >> 4) * 8;
                ldmx4(bh, smem_u32(SB_h + r * TPAD + cc));
                ldmx4(bl, smem_u32(SB_l + r * TPAD + cc));
#pragma unroll
                for (int ma = 0; ma < 2; ma++) {
#pragma unroll
                    for (int sub = 0; sub < 2; sub++) {
                        int nb = nb2 * 2 + sub;
                        mma16816(acc[ma][nb], ah[ma], bh[sub], bh[sub + 2]);
                        mma16816(acc[ma][nb], ah[ma], bl[sub], bl[sub + 2]);
                        mma16816(acc[ma][nb], al[ma], bh[sub], bh[sub + 2]);
                    }
                }
            }
        }
        __syncthreads();
    }

#pragma unroll
    for (int ma = 0; ma < 2; ma++) {
#pragma unroll
        for (int nb = 0; nb < 8; nb++) {
            int r0 = bm + wm * 32 + ma * 16 + (lane >> 2);
            int cc = bn + wn * 64 + nb * 8 + (lane & 3) * 2;
            float* p0 = C + (size_t)r0 * ldc + cc;
            float* p1 = C + (size_t)(r0 + 8) * ldc + cc;
            float2 v0 = make_float2(acc[ma][nb][0], acc[ma][nb][1]);
            float2 v1 = make_float2(acc[ma][nb][2], acc[ma][nb][3]);
            if (ACC) {
                float2 o0 = *(float2*)p0, o1 = *(float2*)p1;
                v0.x += o0.x; v0.y += o0.y;
                v1.x += o1.x; v1.y += o1.y;
            }
            *(float2*)p0 = v0;
            *(float2*)p1 = v1;
        }
    }
}

// ------------------------------------------------------------- conv+silu --
__global__ void conv_silu_kernel(const float* __restrict__ xz,
                                 const float* __restrict__ w,
                                 const float* __restrict__ b,
                                 float* __restrict__ uc)
{
    int idx = blockIdx.x * 256 + threadIdx.x;   // over L*DI
    int l = idx >> 11;
    int d = idx & (DI - 1);
    float s = b[d];
#pragma unroll
    for (int k = 0; k < 4; k++) {
        int tl = l + k - 3;
        if (tl >= 0) s += xz[(size_t)tl * (2*DI) + d] * __ldg(&w[d * 4 + k]);
    }
    uc[idx] = s / (1.f + __expf(-s));
}

// ------------------------------------------------------------------ xproj --
__global__ void __launch_bounds__(256) xproj_kernel(
    const float* __restrict__ uc, const float* __restrict__ W,
    float* __restrict__ xdbl)
{
    __shared__ float sW[96][65];
    __shared__ float sU[8][64];
    const int tid = threadIdx.x;
    const int l0 = blockIdx.x * 8;
    const int tx = tid & 31;
    const int ty = tid >> 5;
    float acc0 = 0.f, acc1 = 0.f, acc2 = 0.f;

    for (int k0 = 0; k0 < DI; k0 += 64) {
        __syncthreads();
#pragma unroll
        for (int i = 0; i < 24; i++) {
            int v = tid + i * 256;
            int ee = v >> 6, rr = v & 63;
            sW[ee][rr] = W[(size_t)ee * DI + k0 + rr];
        }
        {
            int v = tid;
            int ll = v >> 6, rr = v & 63;
            sU[ll][rr] = uc[(size_t)(l0 + ll) * DI + k0 + rr];
            v = tid + 256; ll = v >> 6; rr = v & 63;
            sU[ll][rr] = uc[(size_t)(l0 + ll) * DI + k0 + rr];
        }
        __syncthreads();
#pragma unroll
        for (int r = 0; r < 64; r++) {
            float uv = sU[ty][r];
            acc0 = fmaf(uv, sW[tx][r], acc0);
            acc1 = fmaf(uv, sW[32 + tx][r], acc1);
            acc2 = fmaf(uv, sW[64 + tx][r], acc2);
        }
    }
    size_t base = (size_t)(l0 + ty) * 96;
    xdbl[base + tx]      = acc0;
    xdbl[base + 32 + tx] = acc1;
    xdbl[base + 64 + tx] = acc2;
}

// --------------------------------------------------------------------- dt --
__global__ void __launch_bounds__(256) dt_kernel(
    const float* __restrict__ xdbl, const float* __restrict__ dtw,
    const float* __restrict__ dtb, float* __restrict__ delta)
{
    __shared__ float sW[128][65];
    __shared__ float sR[32][64];
    const int tid = threadIdx.x;
    const int d0 = blockIdx.x * 128;
    const int l0 = blockIdx.y * 32;
#pragma unroll
    for (int i = 0; i < 32; i++) {
        int v = tid + i * 256;
        int dd = v >> 6, rr = v & 63;
        sW[dd][rr] = dtw[(size_t)(d0 + dd) * 64 + rr];
    }
#pragma unroll
    for (int i = 0; i < 8; i++) {
        int v = tid + i * 256;
        int ll = v >> 6, rr = v & 63;
        sR[ll][rr] = xdbl[(size_t)(l0 + ll) * 96 + rr];
    }
    __syncthreads();
    const int tx = tid & 31;
    const int ty = tid >> 5;
    float acc[4][4];
#pragma unroll
    for (int i = 0; i < 4; i++)
#pragma unroll
        for (int j = 0; j < 4; j++) acc[i][j] = 0.f;
#pragma unroll
    for (int r = 0; r < 64; r++) {
        float rv[4], wv[4];
#pragma unroll
        for (int i = 0; i < 4; i++) rv[i] = sR[ty * 4 + i][r];
#pragma unroll
        for (int j = 0; j < 4; j++) wv[j] = sW[j * 32 + tx][r];
#pragma unroll
        for (int i = 0; i < 4; i++)
#pragma unroll
            for (int j = 0; j < 4; j++)
                acc[i][j] = fmaf(rv[i], wv[j], acc[i][j]);
    }
#pragma unroll
    for (int i = 0; i < 4; i++)
#pragma unroll
        for (int j = 0; j < 4; j++) {
            int d = d0 + j * 32 + tx;
            float xv = acc[i][j] + __ldg(&dtb[d]);
            float sp = fmaxf(xv, 0.f) + log1pf(__expf(-fabsf(xv)));
            delta[(size_t)(l0 + ty * 4 + i) * DI + d] = sp;
        }
}

// ------------------------------------------------------------------ A prep --
__global__ void set_flag_kernel() { g_flag = 1; }

__global__ void prepA_kernel(const float* __restrict__ Alog)
{
    int i = blockIdx.x * 256 + threadIdx.x;
    float a = -expf(Alog[i]);
    g_A[i] = a;
    int n = i & 15;
    if (fabsf(a + (float)(n + 1)) > 1e-5f * (float)(n + 1)) g_flag = 0;
}

// --------------------------------------------------- scan pass 1: local ----
// grid (NCH, DI/128), block 128. Local scan per chunk with h_in = 0.
// Writes yloc (incl. u*D), cumulative in-chunk delta S_t, chunk-final h, sumD.
__global__ void __launch_bounds__(128) scan1_kernel(
    const float* __restrict__ delta, const float* __restrict__ xdbl,
    const float* __restrict__ uc, const float* __restrict__ Amat,
    const float* __restrict__ Dsk,
    float* __restrict__ gS, float* __restrict__ gY,
    float* __restrict__ hend, float* __restrict__ chsum)
{
    const int c = blockIdx.x;
    const int d = blockIdx.y * 128 + threadIdx.x;
    __shared__ float sBC[CHT][32];
    for (int i = threadIdx.x; i < CHT * 8; i += 128) {     // float4 units
        int tt = i >> 3, p = (i & 7) << 2;
        *(float4*)&sBC[tt][p] =
            *(const float4*)(xdbl + (size_t)(c * CHT + tt) * 96 + 64 + p);
    }
    __syncthreads();

    float a[NSTATE], h[NSTATE];
#pragma unroll
    for (int n = 0; n < NSTATE; n++) { a[n] = Amat[d * NSTATE + n]; h[n] = 0.f; }
    const float dsk = Dsk[d];
    const int fast = g_flag;
    float S = 0.f;

    const float* dp = delta + (size_t)c * CHT * DI + d;
    const float* up = uc    + (size_t)c * CHT * DI + d;
    float* Sp = gS + (size_t)c * CHT * DI + d;
    float* Yp = gY + (size_t)c * CHT * DI + d;

    for (int tt = 0; tt < CHT; tt++) {
        float dl = dp[(size_t)tt * DI];
        float u  = up[(size_t)tt * DI];
        S += dl;
        Sp[(size_t)tt * DI] = S;
        float du = dl * u;
        float ac0 = 0.f, ac1 = 0.f, ac2 = 0.f, ac3 = 0.f;
        if (fast) {
            float p1 = __expf(-dl);
            float p2 = p1*p1,  p3 = p2*p1,  p4 = p2*p2;
            float p5 = p3*p2,  p6 = p3*p3,  p7 = p4*p3,  p8 = p4*p4;
            float p9 = p5*p4,  p10 = p5*p5, p11 = p6*p5, p12 = p6*p6;
            float p13 = p7*p6, p14 = p7*p7, p15 = p8*p7, p16 = p8*p8;
            float e[16] = {p1,p2,p3,p4,p5,p6,p7,p8,p9,p10,p11,p12,p13,p14,p15,p16};
#pragma unroll
            for (int n = 0; n < NSTATE; n += 4) {
                h[n+0] = fmaf(e[n+0], h[n+0], du * sBC[tt][n+0]);
                ac0 = fmaf(h[n+0], sBC[tt][16+n+0], ac0);
                h[n+1] = fmaf(e[n+1], h[n+1], du * sBC[tt][n+1]);
                ac1 = fmaf(h[n+1], sBC[tt][16+n+1], ac1);
                h[n+2] = fmaf(e[n+2], h[n+2], du * sBC[tt][n+2]);
                ac2 = fmaf(h[n+2], sBC[tt][16+n+2], ac2);
                h[n+3] = fmaf(e[n+3], h[n+3], du * sBC[tt][n+3]);
                ac3 = fmaf(h[n+3], sBC[tt][16+n+3], ac3);
            }
        } else {
#pragma unroll
            for (int n = 0; n < NSTATE; n += 4) {
                float e0 = __expf(dl * a[n+0]);
                float e1 = __expf(dl * a[n+1]);
                float e2 = __expf(dl * a[n+2]);
                float e3 = __expf(dl * a[n+3]);
                h[n+0] = fmaf(e0, h[n+0], du * sBC[tt][n+0]);
                ac0 = fmaf(h[n+0], sBC[tt][16+n+0], ac0);
                h[n+1] = fmaf(e1, h[n+1], du * sBC[tt][n+1]);
                ac1 = fmaf(h[n+1], sBC[tt][16+n+1], ac1);
                h[n+2] = fmaf(e2, h[n+2], du * sBC[tt][n+2]);
                ac2 = fmaf(h[n+2], sBC[tt][16+n+2], ac2);
                h[n+3] = fmaf(e3, h[n+3], du * sBC[tt][n+3]);
                ac3 = fmaf(h[n+3], sBC[tt][16+n+3], ac3);
            }
        }
        float acc = (ac0 + ac1) + (ac2 + ac3);
        Yp[(size_t)tt * DI] = fmaf(u, dsk, acc);
    }

    float* hp = hend + ((size_t)c * DI + d) * NSTATE;
#pragma unroll
    for (int n = 0; n < NSTATE; n += 4)
        *(float4*)(hp + n) = make_float4(h[n], h[n+1], h[n+2], h[n+3]);
    chsum[c * DI + d] = S;
}

// ------------------------------------------- scan pass 2: chunk combine ----
// one thread per (d, n): 16 sequential chunk steps.
__global__ void scan2_kernel(const float* __restrict__ Amat,
                             const float* __restrict__ hend,
                             const float* __restrict__ chsum,
                             float* __restrict__ hin)
{
    int i = blockIdx.x * 256 + threadIdx.x;   // < DI*NSTATE
    int d = i >> 4, n = i & 15;
    const int fast = g_flag;
    float an = fast ? -(float)(n + 1) : Amat[i];
    float h = 0.f;
#pragma unroll
    for (int c = 0; c < NCH; c++) {
        hin[((size_t)c * DI + d) * NSTATE + n] = h;
        float f = __expf(an * chsum[c * DI + d]);
        h = hend[((size_t)c * DI + d) * NSTATE + n] + f * h;
    }
}

// --------------------------------------------- scan pass 3: fixup + gate ---
// grid (NCH, DI/128), block 128.
__global__ void __launch_bounds__(128) scan3_kernel(
    const float* __restrict__ gS, const float* __restrict__ gY,
    const float* __restrict__ xz, const float* __restrict__ xdbl,
    const float* __restrict__ hin, const float* __restrict__ Amat,
    bf16* __restrict__ ygh, bf16* __restrict__ ygl)
{
    const int c = blockIdx.x;
    const int d = blockIdx.y * 128 + threadIdx.x;
    __shared__ float sC[CHT][16];
    for (int i = threadIdx.x; i < CHT * 4; i += 128) {     // float4 units
        int tt = i >> 2, p = (i & 3) << 2;
        *(float4*)&sC[tt][p] =
            *(const float4*)(xdbl + (size_t)(c * CHT + tt) * 96 + 80 + p);
    }
    __syncthreads();

    float hi_[NSTATE], a[NSTATE];
    const float* hp = hin + ((size_t)c * DI + d) * NSTATE;
#pragma unroll
    for (int n = 0; n < NSTATE; n += 4) {
        float4 v = *(const float4*)(hp + n);
        hi_[n] = v.x; hi_[n+1] = v.y; hi_[n+2] = v.z; hi_[n+3] = v.w;
    }
    const int fast = g_flag;
    if (!fast) {
#pragma unroll
        for (int n = 0; n < NSTATE; n++) a[n] = Amat[d * NSTATE + n];
    }

    const float* Sp = gS + (size_t)c * CHT * DI + d;
    const float* Yp = gY + (size_t)c * CHT * DI + d;
    const float* zp = xz + (size_t)c * CHT * (2*DI) + DI + d;
    bf16* oh = ygh + (size_t)c * CHT * DI + d;
    bf16* ol = ygl + (size_t)c * CHT * DI + d;

    for (int tt = 0; tt < CHT; tt++) {
        float S  = Sp[(size_t)tt * DI];
        float yl = Yp[(size_t)tt * DI];
        float zz = zp[(size_t)tt * (2*DI)];
        float acc = 0.f;
        if (fast) {
            float p1 = __expf(-S);
            float p2 = p1*p1,  p3 = p2*p1,  p4 = p2*p2;
            float p5 = p3*p2,  p6 = p3*p3,  p7 = p4*p3,  p8 = p4*p4;
            float p9 = p5*p4,  p10 = p5*p5, p11 = p6*p5, p12 = p6*p6;
            float p13 = p7*p6, p14 = p7*p7, p15 = p8*p7, p16 = p8*p8;
            float e[16] = {p1,p2,p3,p4,p5,p6,p7,p8,p9,p10,p11,p12,p13,p14,p15,p16};
#pragma unroll
            for (int n = 0; n < NSTATE; n++)
                acc = fmaf(e[n] * hi_[n], sC[tt][n], acc);
        } else {
#pragma unroll
            for (int n = 0; n < NSTATE; n++)
                acc = fmaf(__expf(a[n] * S) * hi_[n], sC[tt][n], acc);
        }
        float y = yl + acc;
        float sg = zz / (1.f + __expf(-zz));
        float r = y * sg;
        bf16 hh, ll; split_bf16(r, hh, ll);
        oh[(size_t)tt * DI] = hh;
        ol[(size_t)tt * DI] = ll;
    }
}

// ------------------------------------------------------------------ launch --
extern "C" void kernel_launch(void* const* d_in, const int* in_sizes, int n_in,
                              void* d_out, int out_size)
{
    const float* x      = (const float*)d_in[0];
    const float* norm_w = (const float*)d_in[1];
    const float* in_w   = (const float*)d_in[2];
    const float* conv_w = (const float*)d_in[3];
    const float* conv_b = (const float*)d_in[4];
    const float* xproj_w= (const float*)d_in[5];
    const float* dt_w   = (const float*)d_in[6];
    const float* dt_b   = (const float*)d_in[7];
    const float* A_log  = (const float*)d_in[8];
    const float* D_skip = (const float*)d_in[9];
    const float* out_w  = (const float*)d_in[10];
    float* out = (float*)d_out;

    float *xz, *uc, *xdbl, *delta, *Amat;
    float *S, *yloc, *hend, *hin, *chsum;
    bf16 *xnh, *xnl, *ygh, *ygl, *wih, *wil, *woh, *wol;
    cudaGetSymbolAddress((void**)&xz,    g_xz);
    cudaGetSymbolAddress((void**)&uc,    g_uc);
    cudaGetSymbolAddress((void**)&xdbl,  g_xdbl);
    cudaGetSymbolAddress((void**)&delta, g_delta);
    cudaGetSymbolAddress((void**)&Amat,  g_A);
    cudaGetSymbolAddress((void**)&S,     g_S);
    cudaGetSymbolAddress((void**)&yloc,  g_yloc);
    cudaGetSymbolAddress((void**)&hend,  g_hend);
    cudaGetSymbolAddress((void**)&hin,   g_hin);
    cudaGetSymbolAddress((void**)&chsum, g_chsum);
    cudaGetSymbolAddress((void**)&xnh,   g_xnh);
    cudaGetSymbolAddress((void**)&xnl,   g_xnl);
    cudaGetSymbolAddress((void**)&ygh,   g_ygh);
    cudaGetSymbolAddress((void**)&ygl,   g_ygl);
    cudaGetSymbolAddress((void**)&wih,   g_wih);
    cudaGetSymbolAddress((void**)&wil,   g_wil);
    cudaGetSymbolAddress((void**)&woh,   g_woh);
    cudaGetSymbolAddress((void**)&wol,   g_wol);

    cudaFuncSetAttribute(hmma_gemm<false>,
                         cudaFuncAttributeMaxDynamicSharedMemorySize, HG_SMEM);
    cudaFuncSetAttribute(hmma_gemm<true>,
                         cudaFuncAttributeMaxDynamicSharedMemorySize, HG_SMEM);

    // residual stream init: out = x
    cudaMemcpyAsync(out, x, (size_t)LSEQ * DMODEL * sizeof(float),
                    cudaMemcpyDeviceToDevice, 0);

    for (int lyr = 0; lyr < NL; lyr++) {
        const float* nw  = norm_w  + (size_t)lyr * DMODEL;
        const float* iw  = in_w    + (size_t)lyr * (2*DI) * DMODEL;
        const float* cw  = conv_w  + (size_t)lyr * DI * 4;
        const float* cb  = conv_b  + (size_t)lyr * DI;
        const float* xw  = xproj_w + (size_t)lyr * 96 * DI;
        const float* dw  = dt_w    + (size_t)lyr * DI * DTR;
        const float* db  = dt_b    + (size_t)lyr * DI;
        const float* al  = A_log   + (size_t)lyr * DI * NSTATE;
        const float* ds  = D_skip  + (size_t)lyr * DI;
        const float* ow  = out_w   + (size_t)lyr * DMODEL * DI;

        cvt_kernel<<<(2*DI*DMODEL)/256, 256>>>(iw, wih, wil);
        cvt_kernel<<<(DMODEL*DI)/256, 256>>>(ow, woh, wol);

        rmsnorm_kernel<<<LSEQ, 256>>>(out, nw, xnh, xnl);
        hmma_gemm<false><<<dim3((2*DI)/128, LSEQ/128), 256, HG_SMEM>>>(
            xnh, xnl, wih, wil, xz, 2*DI, DMODEL);
        conv_silu_kernel<<<(LSEQ * DI) / 256, 256>>>(xz, cw, cb, uc);
        xproj_kernel<<<LSEQ / 8, 256>>>(uc, xw, xdbl);
        dt_kernel<<<dim3(DI/128, LSEQ/32), 256>>>(xdbl, dw, db, delta);
        set_flag_kernel<<<1, 1>>>();
        prepA_kernel<<<(DI * NSTATE) / 256, 256>>>(al);

        scan1_kernel<<<dim3(NCH, DI/128), 128>>>(delta, xdbl, uc, Amat, ds,
                                                 S, yloc, hend, chsum);
        scan2_kernel<<<(DI * NSTATE) / 256, 256>>>(Amat, hend, chsum, hin);
        scan3_kernel<<<dim3(NCH, DI/128), 128>>>(S, yloc, xz, xdbl, hin, Amat,
                                                 ygh, ygl);

        hmma_gemm<true><<<dim3(DMODEL/128, LSEQ/128), 256, HG_SMEM>>>(
            ygh, ygl, woh, wol, out, DMODEL, DI);
    }
}

// round 12
// speedup vs baseline: 1.0025x; 1.0025x over previous
#include <cuda_runtime.h>
#include <cuda_bf16.h>
#include <math.h>
#include <stdint.h>

// ---------------------------------------------------------------------------
// MambaDecoder: B=1, L=1024, D=1024, NL=4, DI=2048, N=16, DTR=64, K=4
// Round 7: chunked parallel selective scan (3 passes, full-chip) replacing
// the 64-warp serial scan. GEMMs remain split-bf16 HMMA (R6).
// ---------------------------------------------------------------------------

#define LSEQ 1024
#define DMODEL 1024
#define DI 2048
#define NSTATE 16
#define DTR 64
#define NL 4
#define NCH 16                 // scan chunks
#define CHT 64                 // timesteps per chunk

typedef __nv_bfloat16 bf16;

// ------------------------------------------------------------- PTX helpers --
__device__ __forceinline__ uint32_t smem_u32(const void* p) {
    uint32_t a;
    asm("{ .reg .u64 t; cvta.to.shared.u64 t, %1; cvt.u32.u64 %0, t; }"
        : "=r"(a) : "l"(p));
    return a;
}
__device__ __forceinline__ void cp_async16(uint32_t dst, const void* src) {
    asm volatile("cp.async.cg.shared.global [%0], [%1], 16;"
                 :: "r"(dst), "l"(src));
}
#define CP_COMMIT() asm volatile("cp.async.commit_group;" ::: "memory")
#define CP_WAIT1()  asm volatile("cp.async.wait_group 1;" ::: "memory")
#define CP_WAIT0()  asm volatile("cp.async.wait_group 0;" ::: "memory")

__device__ __forceinline__ void ldmx4(uint32_t* r, uint32_t a) {
    asm volatile("ldmatrix.sync.aligned.m8n8.x4.shared.b16 {%0,%1,%2,%3}, [%4];"
                 : "=r"(r[0]), "=r"(r[1]), "=r"(r[2]), "=r"(r[3]) : "r"(a));
}
__device__ __forceinline__ void mma16816(float* d, const uint32_t* a,
                                         uint32_t b0, uint32_t b1) {
    asm volatile(
        "mma.sync.aligned.m16n8k16.row.col.f32.bf16.bf16.f32 "
        "{%0,%1,%2,%3}, {%4,%5,%6,%7}, {%8,%9}, {%0,%1,%2,%3};"
        : "+f"(d[0]), "+f"(d[1]), "+f"(d[2]), "+f"(d[3])
        : "r"(a[0]), "r"(a[1]), "r"(a[2]), "r"(a[3]), "r"(b0), "r"(b1));
}

// ------------------------------------------------------------------ scratch --
__device__ float g_xz[LSEQ * 2 * DI];      // 16 MB
__device__ float g_uc[LSEQ * DI];          // 8 MB
__device__ float g_xdbl[LSEQ * 96];        // 0.4 MB
__device__ float g_delta[LSEQ * DI];       // 8 MB
__device__ float g_A[DI * NSTATE];
__device__ int   g_flag;
// chunked-scan scratch
__device__ float g_S[LSEQ * DI];           // 8 MB  cumulative delta (in-chunk)
__device__ float g_yloc[LSEQ * DI];        // 8 MB  local scan output
__device__ float g_hend[NCH * DI * NSTATE];// 2 MB  chunk-final local h
__device__ float g_hin[NCH * DI * NSTATE]; // 2 MB  chunk input state
__device__ float g_chsum[NCH * DI];        // 128 KB chunk delta sums
// split-bf16 operands
__device__ bf16 g_xnh[LSEQ * DMODEL];
__device__ bf16 g_xnl[LSEQ * DMODEL];
__device__ bf16 g_ygh[LSEQ * DI];
__device__ bf16 g_ygl[LSEQ * DI];
__device__ bf16 g_wih[2 * DI * DMODEL];    // in_w hi  (4096x1024)
__device__ bf16 g_wil[2 * DI * DMODEL];    // in_w lo
__device__ bf16 g_woh[DMODEL * DI];        // out_w hi (1024x2048)
__device__ bf16 g_wol[DMODEL * DI];        // out_w lo

__device__ __forceinline__ void split_bf16(float v, bf16& h, bf16& l) {
    h = __float2bfloat16(v);
    l = __float2bfloat16(v - __bfloat162float(h));
}

// ------------------------------------------------------------------ convert --
__global__ void cvt_kernel(const float* __restrict__ src,
                           bf16* __restrict__ hi, bf16* __restrict__ lo)
{
    int i = blockIdx.x * 256 + threadIdx.x;
    bf16 h, l;
    split_bf16(src[i], h, l);
    hi[i] = h; lo[i] = l;
}

// ---------------------------------------------------------------- rmsnorm --
__global__ void rmsnorm_kernel(const float* __restrict__ x,
                               const float* __restrict__ w,
                               bf16* __restrict__ oh, bf16* __restrict__ ol)
{
    int l = blockIdx.x;
    int t = threadIdx.x;            // 256 threads, 4 floats each
    const float4* xr = (const float4*)(x + l * DMODEL);
    float4 v = xr[t];
    float ss = v.x*v.x + v.y*v.y + v.z*v.z + v.w*v.w;
#pragma unroll
    for (int o = 16; o > 0; o >>= 1) ss += __shfl_xor_sync(0xffffffffu, ss, o);
    __shared__ float sred[8];
    if ((t & 31) == 0) sred[t >> 5] = ss;
    __syncthreads();
    float tot = 0.f;
#pragma unroll
    for (int i = 0; i < 8; i++) tot += sred[i];
    float rs = rsqrtf(tot * (1.0f / DMODEL) + 1e-5f);
    float4 wv = ((const float4*)w)[t];
    float o0 = v.x*rs*wv.x, o1 = v.y*rs*wv.y, o2 = v.z*rs*wv.z, o3 = v.w*rs*wv.w;
    size_t base = (size_t)l * DMODEL + t * 4;
    bf16 h, lo_;
    split_bf16(o0, h, lo_); oh[base+0] = h; ol[base+0] = lo_;
    split_bf16(o1, h, lo_); oh[base+1] = h; ol[base+1] = lo_;
    split_bf16(o2, h, lo_); oh[base+2] = h; ol[base+2] = lo_;
    split_bf16(o3, h, lo_); oh[base+3] = h; ol[base+3] = lo_;
}

// ------------------------------------------------- split-bf16 HMMA GEMM ----
// C[.,ldc] (+)= (Ah+Al)[M,K] * (Bh+Bl)[N,K]^T  (drop Al*Bl)
#define TPAD 40
#define TILE_E (128 * TPAD)
#define HG_SMEM (2 * 4 * TILE_E * 2)    // 81920 bytes

__device__ __forceinline__ void load_stage(
    bf16* s0, bf16* s1, bf16* s2, bf16* s3,
    const bf16* __restrict__ Ah, const bf16* __restrict__ Al,
    const bf16* __restrict__ Bh, const bf16* __restrict__ Bl,
    int bm, int bn, int K, int k0, int tid)
{
#pragma unroll
    for (int i = 0; i < 2; i++) {
        int j = tid + i * 256;          // 0..511
        int row = j >> 2, seg = j & 3;
        int off = row * TPAD + seg * 8;
        size_t ga = (size_t)(bm + row) * K + k0 + seg * 8;
        size_t gb = (size_t)(bn + row) * K + k0 + seg * 8;
        cp_async16(smem_u32(s0 + off), Ah + ga);
        cp_async16(smem_u32(s1 + off), Al + ga);
        cp_async16(smem_u32(s2 + off), Bh + gb);
        cp_async16(smem_u32(s3 + off), Bl + gb);
    }
}

template<bool ACC>
__global__ void __launch_bounds__(256, 2) hmma_gemm(
    const bf16* __restrict__ Ah, const bf16* __restrict__ Al,
    const bf16* __restrict__ Bh, const bf16* __restrict__ Bl,
    float* __restrict__ C, int ldc, int K)
{
    extern __shared__ __align__(16) bf16 sm[];
    const int tid = threadIdx.x;
    const int lane = tid & 31;
    const int wid = tid >> 5;
    const int wm = wid & 3;
    const int wn = wid >> 2;
    const int bm = blockIdx.y * 128;
    const int bn = blockIdx.x * 128;

    float acc[2][8][4];
#pragma unroll
    for (int i = 0; i < 2; i++)
#pragma unroll
        for (int j = 0; j < 8; j++)
#pragma unroll
            for (int k = 0; k < 4; k++) acc[i][j][k] = 0.f;

    const int nch = K >> 5;
    load_stage(sm, sm + TILE_E, sm + 2*TILE_E, sm + 3*TILE_E,
               Ah, Al, Bh, Bl, bm, bn, K, 0, tid);
    CP_COMMIT();

    for (int c = 0; c < nch; c++) {
        if (c + 1 < nch) {
            bf16* st = sm + ((c + 1) & 1) * 4 * TILE_E;
            load_stage(st, st + TILE_E, st + 2*TILE_E, st + 3*TILE_E,
                       Ah, Al, Bh, Bl, bm, bn, K, (c + 1) << 5, tid);
            CP_COMMIT();
            CP_WAIT1();
        } else {
            CP_WAIT0();
        }
        __syncthreads();

        bf16* SA_h = sm + (c & 1) * 4 * TILE_E;
        bf16* SA_l = SA_h + TILE_E;
        bf16* SB_h = SA_h + 2 * TILE_E;
        bf16* SB_l = SA_h + 3 * TILE_E;

#pragma unroll
        for (int ks = 0; ks < 32; ks += 16) {
            uint32_t ah[2][4], al[2][4];
#pragma unroll
            for (int ma = 0; ma < 2; ma++) {
                int r = wm * 32 + ma * 16 + (lane & 15);
                int cc = ks + (lane >> 4) * 8;
                ldmx4(ah[ma], smem_u32(SA_h + r * TPAD + cc));
                ldmx4(al[ma], smem_u32(SA_l + r * TPAD + cc));
            }
#pragma unroll
            for (int nb2 = 0; nb2 < 4; nb2++) {
                uint32_t bh[4], bl[4];
                int r = wn * 64 + nb2 * 16 + (lane & 15);
                int cc = ks + (lane >> 4) * 8;
                ldmx4(bh, smem_u32(SB_h + r * TPAD + cc));
                ldmx4(bl, smem_u32(SB_l + r * TPAD + cc));
#pragma unroll
                for (int ma = 0; ma < 2; ma++) {
#pragma unroll
                    for (int sub = 0; sub < 2; sub++) {
                        int nb = nb2 * 2 + sub;
                        mma16816(acc[ma][nb], ah[ma], bh[sub], bh[sub + 2]);
                        mma16816(acc[ma][nb], ah[ma], bl[sub], bl[sub + 2]);
                        mma16816(acc[ma][nb], al[ma], bh[sub], bh[sub + 2]);
                    }
                }
            }
        }
        __syncthreads();
    }

#pragma unroll
    for (int ma = 0; ma < 2; ma++) {
#pragma unroll
        for (int nb = 0; nb < 8; nb++) {
            int r0 = bm + wm * 32 + ma * 16 + (lane >> 2);
            int cc = bn + wn * 64 + nb * 8 + (lane & 3) * 2;
            float* p0 = C + (size_t)r0 * ldc + cc;
            float* p1 = C + (size_t)(r0 + 8) * ldc + cc;
            float2 v0 = make_float2(acc[ma][nb][0], acc[ma][nb][1]);
            float2 v1 = make_float2(acc[ma][nb][2], acc[ma][nb][3]);
            if (ACC) {
                float2 o0 = *(float2*)p0, o1 = *(float2*)p1;
                v0.x += o0.x; v0.y += o0.y;
                v1.x += o1.x; v1.y += o1.y;
            }
            *(float2*)p0 = v0;
            *(float2*)p1 = v1;
        }
    }
}

// ------------------------------------------------------------- conv+silu --
__global__ void conv_silu_kernel(const float* __restrict__ xz,
                                 const float* __restrict__ w,
                                 const float* __restrict__ b,
                                 float* __restrict__ uc)
{
    int idx = blockIdx.x * 256 + threadIdx.x;   // over L*DI
    int l = idx >> 11;
    int d = idx & (DI - 1);
    float s = b[d];
#pragma unroll
    for (int k = 0; k < 4; k++) {
        int tl = l + k - 3;
        if (tl >= 0) s += xz[(size_t)tl * (2*DI) + d] * __ldg(&w[d * 4 + k]);
    }
    uc[idx] = s / (1.f + __expf(-s));
}

// ------------------------------------------------------------------ xproj --
__global__ void __launch_bounds__(256) xproj_kernel(
    const float* __restrict__ uc, const float* __restrict__ W,
    float* __restrict__ xdbl)
{
    __shared__ float sW[96][65];
    __shared__ float sU[8][64];
    const int tid = threadIdx.x;
    const int l0 = blockIdx.x * 8;
    const int tx = tid & 31;
    const int ty = tid >> 5;
    float acc0 = 0.f, acc1 = 0.f, acc2 = 0.f;

    for (int k0 = 0; k0 < DI; k0 += 64) {
        __syncthreads();
#pragma unroll
        for (int i = 0; i < 24; i++) {
            int v = tid + i * 256;
            int ee = v >> 6, rr = v & 63;
            sW[ee][rr] = W[(size_t)ee * DI + k0 + rr];
        }
        {
            int v = tid;
            int ll = v >> 6, rr = v & 63;
            sU[ll][rr] = uc[(size_t)(l0 + ll) * DI + k0 + rr];
            v = tid + 256; ll = v >> 6; rr = v & 63;
            sU[ll][rr] = uc[(size_t)(l0 + ll) * DI + k0 + rr];
        }
        __syncthreads();
#pragma unroll
        for (int r = 0; r < 64; r++) {
            float uv = sU[ty][r];
            acc0 = fmaf(uv, sW[tx][r], acc0);
            acc1 = fmaf(uv, sW[32 + tx][r], acc1);
            acc2 = fmaf(uv, sW[64 + tx][r], acc2);
        }
    }
    size_t base = (size_t)(l0 + ty) * 96;
    xdbl[base + tx]      = acc0;
    xdbl[base + 32 + tx] = acc1;
    xdbl[base + 64 + tx] = acc2;
}

// --------------------------------------------------------------------- dt --
__global__ void __launch_bounds__(256) dt_kernel(
    const float* __restrict__ xdbl, const float* __restrict__ dtw,
    const float* __restrict__ dtb, float* __restrict__ delta)
{
    __shared__ float sW[128][65];
    __shared__ float sR[32][64];
    const int tid = threadIdx.x;
    const int d0 = blockIdx.x * 128;
    const int l0 = blockIdx.y * 32;
#pragma unroll
    for (int i = 0; i < 32; i++) {
        int v = tid + i * 256;
        int dd = v >> 6, rr = v & 63;
        sW[dd][rr] = dtw[(size_t)(d0 + dd) * 64 + rr];
    }
#pragma unroll
    for (int i = 0; i < 8; i++) {
        int v = tid + i * 256;
        int ll = v >> 6, rr = v & 63;
        sR[ll][rr] = xdbl[(size_t)(l0 + ll) * 96 + rr];
    }
    __syncthreads();
    const int tx = tid & 31;
    const int ty = tid >> 5;
    float acc[4][4];
#pragma unroll
    for (int i = 0; i < 4; i++)
#pragma unroll
        for (int j = 0; j < 4; j++) acc[i][j] = 0.f;
#pragma unroll
    for (int r = 0; r < 64; r++) {
        float rv[4], wv[4];
#pragma unroll
        for (int i = 0; i < 4; i++) rv[i] = sR[ty * 4 + i][r];
#pragma unroll
        for (int j = 0; j < 4; j++) wv[j] = sW[j * 32 + tx][r];
#pragma unroll
        for (int i = 0; i < 4; i++)
#pragma unroll
            for (int j = 0; j < 4; j++)
                acc[i][j] = fmaf(rv[i], wv[j], acc[i][j]);
    }
#pragma unroll
    for (int i = 0; i < 4; i++)
#pragma unroll
        for (int j = 0; j < 4; j++) {
            int d = d0 + j * 32 + tx;
            float xv = acc[i][j] + __ldg(&dtb[d]);
            float sp = fmaxf(xv, 0.f) + log1pf(__expf(-fabsf(xv)));
            delta[(size_t)(l0 + ty * 4 + i) * DI + d] = sp;
        }
}

// ------------------------------------------------------------------ A prep --
__global__ void set_flag_kernel() { g_flag = 1; }

__global__ void prepA_kernel(const float* __restrict__ Alog)
{
    int i = blockIdx.x * 256 + threadIdx.x;
    float a = -expf(Alog[i]);
    g_A[i] = a;
    int n = i & 15;
    if (fabsf(a + (float)(n + 1)) > 1e-5f * (float)(n + 1)) g_flag = 0;
}

// --------------------------------------------------- scan pass 1: local ----
// grid (NCH, DI/128), block 128. Local scan per chunk with h_in = 0.
// Writes yloc (incl. u*D), cumulative in-chunk delta S_t, chunk-final h, sumD.
__global__ void __launch_bounds__(128) scan1_kernel(
    const float* __restrict__ delta, const float* __restrict__ xdbl,
    const float* __restrict__ uc, const float* __restrict__ Amat,
    const float* __restrict__ Dsk,
    float* __restrict__ gS, float* __restrict__ gY,
    float* __restrict__ hend, float* __restrict__ chsum)
{
    const int c = blockIdx.x;
    const int d = blockIdx.y * 128 + threadIdx.x;
    __shared__ float sBC[CHT][32];
    for (int i = threadIdx.x; i < CHT * 8; i += 128) {     // float4 units
        int tt = i >> 3, p = (i & 7) << 2;
        *(float4*)&sBC[tt][p] =
            *(const float4*)(xdbl + (size_t)(c * CHT + tt) * 96 + 64 + p);
    }
    __syncthreads();

    float a[NSTATE], h[NSTATE];
#pragma unroll
    for (int n = 0; n < NSTATE; n++) { a[n] = Amat[d * NSTATE + n]; h[n] = 0.f; }
    const float dsk = Dsk[d];
    const int fast = g_flag;
    float S = 0.f;

    const float* dp = delta + (size_t)c * CHT * DI + d;
    const float* up = uc    + (size_t)c * CHT * DI + d;
    float* Sp = gS + (size_t)c * CHT * DI + d;
    float* Yp = gY + (size_t)c * CHT * DI + d;

    for (int tt = 0; tt < CHT; tt++) {
        float dl = dp[(size_t)tt * DI];
        float u  = up[(size_t)tt * DI];
        S += dl;
        Sp[(size_t)tt * DI] = S;
        float du = dl * u;
        float ac0 = 0.f, ac1 = 0.f, ac2 = 0.f, ac3 = 0.f;
        if (fast) {
            float p1 = __expf(-dl);
            float p2 = p1*p1,  p3 = p2*p1,  p4 = p2*p2;
            float p5 = p3*p2,  p6 = p3*p3,  p7 = p4*p3,  p8 = p4*p4;
            float p9 = p5*p4,  p10 = p5*p5, p11 = p6*p5, p12 = p6*p6;
            float p13 = p7*p6, p14 = p7*p7, p15 = p8*p7, p16 = p8*p8;
            float e[16] = {p1,p2,p3,p4,p5,p6,p7,p8,p9,p10,p11,p12,p13,p14,p15,p16};
#pragma unroll
            for (int n = 0; n < NSTATE; n += 4) {
                h[n+0] = fmaf(e[n+0], h[n+0], du * sBC[tt][n+0]);
                ac0 = fmaf(h[n+0], sBC[tt][16+n+0], ac0);
                h[n+1] = fmaf(e[n+1], h[n+1], du * sBC[tt][n+1]);
                ac1 = fmaf(h[n+1], sBC[tt][16+n+1], ac1);
                h[n+2] = fmaf(e[n+2], h[n+2], du * sBC[tt][n+2]);
                ac2 = fmaf(h[n+2], sBC[tt][16+n+2], ac2);
                h[n+3] = fmaf(e[n+3], h[n+3], du * sBC[tt][n+3]);
                ac3 = fmaf(h[n+3], sBC[tt][16+n+3], ac3);
            }
        } else {
#pragma unroll
            for (int n = 0; n < NSTATE; n += 4) {
                float e0 = __expf(dl * a[n+0]);
                float e1 = __expf(dl * a[n+1]);
                float e2 = __expf(dl * a[n+2]);
                float e3 = __expf(dl * a[n+3]);
                h[n+0] = fmaf(e0, h[n+0], du * sBC[tt][n+0]);
                ac0 = fmaf(h[n+0], sBC[tt][16+n+0], ac0);
                h[n+1] = fmaf(e1, h[n+1], du * sBC[tt][n+1]);
                ac1 = fmaf(h[n+1], sBC[tt][16+n+1], ac1);
                h[n+2] = fmaf(e2, h[n+2], du * sBC[tt][n+2]);
                ac2 = fmaf(h[n+2], sBC[tt][16+n+2], ac2);
                h[n+3] = fmaf(e3, h[n+3], du * sBC[tt][n+3]);
                ac3 = fmaf(h[n+3], sBC[tt][16+n+3], ac3);
            }
        }
        float acc = (ac0 + ac1) + (ac2 + ac3);
        Yp[(size_t)tt * DI] = fmaf(u, dsk, acc);
    }

    float* hp = hend + ((size_t)c * DI + d) * NSTATE;
#pragma unroll
    for (int n = 0; n < NSTATE; n += 4)
        *(float4*)(hp + n) = make_float4(h[n], h[n+1], h[n+2], h[n+3]);
    chsum[c * DI + d] = S;
}

// ------------------------------------------- scan pass 2: chunk combine ----
// one thread per (d, n): 16 sequential chunk steps.
__global__ void scan2_kernel(const float* __restrict__ Amat,
                             const float* __restrict__ hend,
                             const float* __restrict__ chsum,
                             float* __restrict__ hin)
{
    int i = blockIdx.x * 256 + threadIdx.x;   // < DI*NSTATE
    int d = i >> 4, n = i & 15;
    const int fast = g_flag;
    float an = fast ? -(float)(n + 1) : Amat[i];
    float h = 0.f;
#pragma unroll
    for (int c = 0; c < NCH; c++) {
        hin[((size_t)c * DI + d) * NSTATE + n] = h;
        float f = __expf(an * chsum[c * DI + d]);
        h = hend[((size_t)c * DI + d) * NSTATE + n] + f * h;
    }
}

// --------------------------------------------- scan pass 3: fixup + gate ---
// grid (NCH, DI/128), block 128.
__global__ void __launch_bounds__(128) scan3_kernel(
    const float* __restrict__ gS, const float* __restrict__ gY,
    const float* __restrict__ xz, const float* __restrict__ xdbl,
    const float* __restrict__ hin, const float* __restrict__ Amat,
    bf16* __restrict__ ygh, bf16* __restrict__ ygl)
{
    const int c = blockIdx.x;
    const int d = blockIdx.y * 128 + threadIdx.x;
    __shared__ float sC[CHT][16];
    for (int i = threadIdx.x; i < CHT * 4; i += 128) {     // float4 units
        int tt = i >> 2, p = (i & 3) << 2;
        *(float4*)&sC[tt][p] =
            *(const float4*)(xdbl + (size_t)(c * CHT + tt) * 96 + 80 + p);
    }
    __syncthreads();

    float hi_[NSTATE], a[NSTATE];
    const float* hp = hin + ((size_t)c * DI + d) * NSTATE;
#pragma unroll
    for (int n = 0; n < NSTATE; n += 4) {
        float4 v = *(const float4*)(hp + n);
        hi_[n] = v.x; hi_[n+1] = v.y; hi_[n+2] = v.z; hi_[n+3] = v.w;
    }
    const int fast = g_flag;
    if (!fast) {
#pragma unroll
        for (int n = 0; n < NSTATE; n++) a[n] = Amat[d * NSTATE + n];
    }

    const float* Sp = gS + (size_t)c * CHT * DI + d;
    const float* Yp = gY + (size_t)c * CHT * DI + d;
    const float* zp = xz + (size_t)c * CHT * (2*DI) + DI + d;
    bf16* oh = ygh + (size_t)c * CHT * DI + d;
    bf16* ol = ygl + (size_t)c * CHT * DI + d;

    for (int tt = 0; tt < CHT; tt++) {
        float S  = Sp[(size_t)tt * DI];
        float yl = Yp[(size_t)tt * DI];
        float zz = zp[(size_t)tt * (2*DI)];
        float acc = 0.f;
        if (fast) {
            float p1 = __expf(-S);
            float p2 = p1*p1,  p3 = p2*p1,  p4 = p2*p2;
            float p5 = p3*p2,  p6 = p3*p3,  p7 = p4*p3,  p8 = p4*p4;
            float p9 = p5*p4,  p10 = p5*p5, p11 = p6*p5, p12 = p6*p6;
            float p13 = p7*p6, p14 = p7*p7, p15 = p8*p7, p16 = p8*p8;
            float e[16] = {p1,p2,p3,p4,p5,p6,p7,p8,p9,p10,p11,p12,p13,p14,p15,p16};
#pragma unroll
            for (int n = 0; n < NSTATE; n++)
                acc = fmaf(e[n] * hi_[n], sC[tt][n], acc);
        } else {
#pragma unroll
            for (int n = 0; n < NSTATE; n++)
                acc = fmaf(__expf(a[n] * S) * hi_[n], sC[tt][n], acc);
        }
        float y = yl + acc;
        float sg = zz / (1.f + __expf(-zz));
        float r = y * sg;
        bf16 hh, ll; split_bf16(r, hh, ll);
        oh[(size_t)tt * DI] = hh;
        ol[(size_t)tt * DI] = ll;
    }
}

// ------------------------------------------------------------------ launch --
extern "C" void kernel_launch(void* const* d_in, const int* in_sizes, int n_in,
                              void* d_out, int out_size)
{
    const float* x      = (const float*)d_in[0];
    const float* norm_w = (const float*)d_in[1];
    const float* in_w   = (const float*)d_in[2];
    const float* conv_w = (const float*)d_in[3];
    const float* conv_b = (const float*)d_in[4];
    const float* xproj_w= (const float*)d_in[5];
    const float* dt_w   = (const float*)d_in[6];
    const float* dt_b   = (const float*)d_in[7];
    const float* A_log  = (const float*)d_in[8];
    const float* D_skip = (const float*)d_in[9];
    const float* out_w  = (const float*)d_in[10];
    float* out = (float*)d_out;

    float *xz, *uc, *xdbl, *delta, *Amat;
    float *S, *yloc, *hend, *hin, *chsum;
    bf16 *xnh, *xnl, *ygh, *ygl, *wih, *wil, *woh, *wol;
    cudaGetSymbolAddress((void**)&xz,    g_xz);
    cudaGetSymbolAddress((void**)&uc,    g_uc);
    cudaGetSymbolAddress((void**)&xdbl,  g_xdbl);
    cudaGetSymbolAddress((void**)&delta, g_delta);
    cudaGetSymbolAddress((void**)&Amat,  g_A);
    cudaGetSymbolAddress((void**)&S,     g_S);
    cudaGetSymbolAddress((void**)&yloc,  g_yloc);
    cudaGetSymbolAddress((void**)&hend,  g_hend);
    cudaGetSymbolAddress((void**)&hin,   g_hin);
    cudaGetSymbolAddress((void**)&chsum, g_chsum);
    cudaGetSymbolAddress((void**)&xnh,   g_xnh);
    cudaGetSymbolAddress((void**)&xnl,   g_xnl);
    cudaGetSymbolAddress((void**)&ygh,   g_ygh);
    cudaGetSymbolAddress((void**)&ygl,   g_ygl);
    cudaGetSymbolAddress((void**)&wih,   g_wih);
    cudaGetSymbolAddress((void**)&wil,   g_wil);
    cudaGetSymbolAddress((void**)&woh,   g_woh);
    cudaGetSymbolAddress((void**)&wol,   g_wol);

    cudaFuncSetAttribute(hmma_gemm<false>,
                         cudaFuncAttributeMaxDynamicSharedMemorySize, HG_SMEM);
    cudaFuncSetAttribute(hmma_gemm<true>,
                         cudaFuncAttributeMaxDynamicSharedMemorySize, HG_SMEM);

    // residual stream init: out = x
    cudaMemcpyAsync(out, x, (size_t)LSEQ * DMODEL * sizeof(float),
                    cudaMemcpyDeviceToDevice, 0);

    for (int lyr = 0; lyr < NL; lyr++) {
        const float* nw  = norm_w  + (size_t)lyr * DMODEL;
        const float* iw  = in_w    + (size_t)lyr * (2*DI) * DMODEL;
        const float* cw  = conv_w  + (size_t)lyr * DI * 4;
        const float* cb  = conv_b  + (size_t)lyr * DI;
        const float* xw  = xproj_w + (size_t)lyr * 96 * DI;
        const float* dw  = dt_w    + (size_t)lyr * DI * DTR;
        const float* db  = dt_b    + (size_t)lyr * DI;
        const float* al  = A_log   + (size_t)lyr * DI * NSTATE;
        const float* ds  = D_skip  + (size_t)lyr * DI;
        const float* ow  = out_w   + (size_t)lyr * DMODEL * DI;

        cvt_kernel<<<(2*DI*DMODEL)/256, 256>>>(iw, wih, wil);
        cvt_kernel<<<(DMODEL*DI)/256, 256>>>(ow, woh, wol);

        rmsnorm_kernel<<<LSEQ, 256>>>(out, nw, xnh, xnl);
        hmma_gemm<false><<<dim3((2*DI)/128, LSEQ/128), 256, HG_SMEM>>>(
            xnh, xnl, wih, wil, xz, 2*DI, DMODEL);
        conv_silu_kernel<<<(LSEQ * DI) / 256, 256>>>(xz, cw, cb, uc);
        xproj_kernel<<<LSEQ / 8, 256>>>(uc, xw, xdbl);
        dt_kernel<<<dim3(DI/128, LSEQ/32), 256>>>(xdbl, dw, db, delta);
        set_flag_kernel<<<1, 1>>>();
        prepA_kernel<<<(DI * NSTATE) / 256, 256>>>(al);

        scan1_kernel<<<dim3(NCH, DI/128), 128>>>(delta, xdbl, uc, Amat, ds,
                                                 S, yloc, hend, chsum);
        scan2_kernel<<<(DI * NSTATE) / 256, 256>>>(Amat, hend, chsum, hin);
        scan3_kernel<<<dim3(NCH, DI/128), 128>>>(S, yloc, xz, xdbl, hin, Amat,
                                                 ygh, ygl);

        hmma_gemm<true><<<dim3(DMODEL/128, LSEQ/128), 256, HG_SMEM>>>(
            ygh, ygl, woh, wol, out, DMODEL, DI);
    }
}

// round 13
// speedup vs baseline: 1.0052x; 1.0026x over previous
#include <cuda_runtime.h>
#include <cuda_bf16.h>
#include <math.h>
#include <stdint.h>

// ---------------------------------------------------------------------------
// MambaDecoder: B=1, L=1024, D=1024, NL=4, DI=2048, N=16, DTR=64, K=4
// Round 7: chunked parallel selective scan (3 passes, full-chip) replacing
// the 64-warp serial scan. GEMMs remain split-bf16 HMMA (R6).
// ---------------------------------------------------------------------------

#define LSEQ 1024
#define DMODEL 1024
#define DI 2048
#define NSTATE 16
#define DTR 64
#define NL 4
#define NCH 16                 // scan chunks
#define CHT 64                 // timesteps per chunk

typedef __nv_bfloat16 bf16;

// ------------------------------------------------------------- PTX helpers --
__device__ __forceinline__ uint32_t smem_u32(const void* p) {
    uint32_t a;
    asm("{ .reg .u64 t; cvta.to.shared.u64 t, %1; cvt.u32.u64 %0, t; }"
        : "=r"(a) : "l"(p));
    return a;
}
__device__ __forceinline__ void cp_async16(uint32_t dst, const void* src) {
    asm volatile("cp.async.cg.shared.global [%0], [%1], 16;"
                 :: "r"(dst), "l"(src));
}
#define CP_COMMIT() asm volatile("cp.async.commit_group;" ::: "memory")
#define CP_WAIT1()  asm volatile("cp.async.wait_group 1;" ::: "memory")
#define CP_WAIT0()  asm volatile("cp.async.wait_group 0;" ::: "memory")

__device__ __forceinline__ void ldmx4(uint32_t* r, uint32_t a) {
    asm volatile("ldmatrix.sync.aligned.m8n8.x4.shared.b16 {%0,%1,%2,%3}, [%4];"
                 : "=r"(r[0]), "=r"(r[1]), "=r"(r[2]), "=r"(r[3]) : "r"(a));
}
__device__ __forceinline__ void mma16816(float* d, const uint32_t* a,
                                         uint32_t b0, uint32_t b1) {
    asm volatile(
        "mma.sync.aligned.m16n8k16.row.col.f32.bf16.bf16.f32 "
        "{%0,%1,%2,%3}, {%4,%5,%6,%7}, {%8,%9}, {%0,%1,%2,%3};"
        : "+f"(d[0]), "+f"(d[1]), "+f"(d[2]), "+f"(d[3])
        : "r"(a[0]), "r"(a[1]), "r"(a[2]), "r"(a[3]), "r"(b0), "r"(b1));
}

// ------------------------------------------------------------------ scratch --
__device__ float g_xz[LSEQ * 2 * DI];      // 16 MB
__device__ float g_uc[LSEQ * DI];          // 8 MB
__device__ float g_xdbl[LSEQ * 96];        // 0.4 MB
__device__ float g_delta[LSEQ * DI];       // 8 MB
__device__ float g_A[DI * NSTATE];
__device__ int   g_flag;
// chunked-scan scratch
__device__ float g_S[LSEQ * DI];           // 8 MB  cumulative delta (in-chunk)
__device__ float g_yloc[LSEQ * DI];        // 8 MB  local scan output
__device__ float g_hend[NCH * DI * NSTATE];// 2 MB  chunk-final local h
__device__ float g_hin[NCH * DI * NSTATE]; // 2 MB  chunk input state
__device__ float g_chsum[NCH * DI];        // 128 KB chunk delta sums
// split-bf16 operands
__device__ bf16 g_xnh[LSEQ * DMODEL];
__device__ bf16 g_xnl[LSEQ * DMODEL];
__device__ bf16 g_ygh[LSEQ * DI];
__device__ bf16 g_ygl[LSEQ * DI];
__device__ bf16 g_wih[2 * DI * DMODEL];    // in_w hi  (4096x1024)
__device__ bf16 g_wil[2 * DI * DMODEL];    // in_w lo
__device__ bf16 g_woh[DMODEL * DI];        // out_w hi (1024x2048)
__device__ bf16 g_wol[DMODEL * DI];        // out_w lo

__device__ __forceinline__ void split_bf16(float v, bf16& h, bf16& l) {
    h = __float2bfloat16(v);
    l = __float2bfloat16(v - __bfloat162float(h));
}

// ------------------------------------------------------------------ convert --
__global__ void cvt_kernel(const float* __restrict__ src,
                           bf16* __restrict__ hi, bf16* __restrict__ lo)
{
    int i = blockIdx.x * 256 + threadIdx.x;
    bf16 h, l;
    split_bf16(src[i], h, l);
    hi[i] = h; lo[i] = l;
}

// ---------------------------------------------------------------- rmsnorm --
__global__ void rmsnorm_kernel(const float* __restrict__ x,
                               const float* __restrict__ w,
                               bf16* __restrict__ oh, bf16* __restrict__ ol)
{
    int l = blockIdx.x;
    int t = threadIdx.x;            // 256 threads, 4 floats each
    const float4* xr = (const float4*)(x + l * DMODEL);
    float4 v = xr[t];
    float ss = v.x*v.x + v.y*v.y + v.z*v.z + v.w*v.w;
#pragma unroll
    for (int o = 16; o > 0; o >>= 1) ss += __shfl_xor_sync(0xffffffffu, ss, o);
    __shared__ float sred[8];
    if ((t & 31) == 0) sred[t >> 5] = ss;
    __syncthreads();
    float tot = 0.f;
#pragma unroll
    for (int i = 0; i < 8; i++) tot += sred[i];
    float rs = rsqrtf(tot * (1.0f / DMODEL) + 1e-5f);
    float4 wv = ((const float4*)w)[t];
    float o0 = v.x*rs*wv.x, o1 = v.y*rs*wv.y, o2 = v.z*rs*wv.z, o3 = v.w*rs*wv.w;
    size_t base = (size_t)l * DMODEL + t * 4;
    bf16 h, lo_;
    split_bf16(o0, h, lo_); oh[base+0] = h; ol[base+0] = lo_;
    split_bf16(o1, h, lo_); oh[base+1] = h; ol[base+1] = lo_;
    split_bf16(o2, h, lo_); oh[base+2] = h; ol[base+2] = lo_;
    split_bf16(o3, h, lo_); oh[base+3] = h; ol[base+3] = lo_;
}

// ------------------------------------------------- split-bf16 HMMA GEMM ----
// C[.,ldc] (+)= (Ah+Al)[M,K] * (Bh+Bl)[N,K]^T  (drop Al*Bl)
#define TPAD 40
#define TILE_E (128 * TPAD)
#define HG_SMEM (2 * 4 * TILE_E * 2)    // 81920 bytes

__device__ __forceinline__ void load_stage(
    bf16* s0, bf16* s1, bf16* s2, bf16* s3,
    const bf16* __restrict__ Ah, const bf16* __restrict__ Al,
    const bf16* __restrict__ Bh, const bf16* __restrict__ Bl,
    int bm, int bn, int K, int k0, int tid)
{
#pragma unroll
    for (int i = 0; i < 2; i++) {
        int j = tid + i * 256;          // 0..511
        int row = j >> 2, seg = j & 3;
        int off = row * TPAD + seg * 8;
        size_t ga = (size_t)(bm + row) * K + k0 + seg * 8;
        size_t gb = (size_t)(bn + row) * K + k0 + seg * 8;
        cp_async16(smem_u32(s0 + off), Ah + ga);
        cp_async16(smem_u32(s1 + off), Al + ga);
        cp_async16(smem_u32(s2 + off), Bh + gb);
        cp_async16(smem_u32(s3 + off), Bl + gb);
    }
}

template<bool ACC>
__global__ void __launch_bounds__(256, 2) hmma_gemm(
    const bf16* __restrict__ Ah, const bf16* __restrict__ Al,
    const bf16* __restrict__ Bh, const bf16* __restrict__ Bl,
    float* __restrict__ C, int ldc, int K)
{
    extern __shared__ __align__(16) bf16 sm[];
    const int tid = threadIdx.x;
    const int lane = tid & 31;
    const int wid = tid >> 5;
    const int wm = wid & 3;
    const int wn = wid >> 2;
    const int bm = blockIdx.y * 128;
    const int bn = blockIdx.x * 128;

    float acc[2][8][4];
#pragma unroll
    for (int i = 0; i < 2; i++)
#pragma unroll
        for (int j = 0; j < 8; j++)
#pragma unroll
            for (int k = 0; k < 4; k++) acc[i][j][k] = 0.f;

    const int nch = K >> 5;
    load_stage(sm, sm + TILE_E, sm + 2*TILE_E, sm + 3*TILE_E,
               Ah, Al, Bh, Bl, bm, bn, K, 0, tid);
    CP_COMMIT();

    for (int c = 0; c < nch; c++) {
        if (c + 1 < nch) {
            bf16* st = sm + ((c + 1) & 1) * 4 * TILE_E;
            load_stage(st, st + TILE_E, st + 2*TILE_E, st + 3*TILE_E,
                       Ah, Al, Bh, Bl, bm, bn, K, (c + 1) << 5, tid);
            CP_COMMIT();
            CP_WAIT1();
        } else {
            CP_WAIT0();
        }
        __syncthreads();

        bf16* SA_h = sm + (c & 1) * 4 * TILE_E;
        bf16* SA_l = SA_h + TILE_E;
        bf16* SB_h = SA_h + 2 * TILE_E;
        bf16* SB_l = SA_h + 3 * TILE_E;

#pragma unroll
        for (int ks = 0; ks < 32; ks += 16) {
            uint32_t ah[2][4], al[2][4];
#pragma unroll
            for (int ma = 0; ma < 2; ma++) {
                int r = wm * 32 + ma * 16 + (lane & 15);
                int cc = ks + (lane >> 4) * 8;
                ldmx4(ah[ma], smem_u32(SA_h + r * TPAD + cc));
                ldmx4(al[ma], smem_u32(SA_l + r * TPAD + cc));
            }
#pragma unroll
            for (int nb2 = 0; nb2 < 4; nb2++) {
                uint32_t bh[4], bl[4];
                int r = wn * 64 + nb2 * 16 + (lane & 15);
                int cc = ks + (lane >> 4) * 8;
                ldmx4(bh, smem_u32(SB_h + r * TPAD + cc));
                ldmx4(bl, smem_u32(SB_l + r * TPAD + cc));
#pragma unroll
                for (int ma = 0; ma < 2; ma++) {
#pragma unroll
                    for (int sub = 0; sub < 2; sub++) {
                        int nb = nb2 * 2 + sub;
                        mma16816(acc[ma][nb], ah[ma], bh[sub], bh[sub + 2]);
                        mma16816(acc[ma][nb], ah[ma], bl[sub], bl[sub + 2]);
                        mma16816(acc[ma][nb], al[ma], bh[sub], bh[sub + 2]);
                    }
                }
            }
        }
        __syncthreads();
    }

#pragma unroll
    for (int ma = 0; ma < 2; ma++) {
#pragma unroll
        for (int nb = 0; nb < 8; nb++) {
            int r0 = bm + wm * 32 + ma * 16 + (lane >> 2);
            int cc = bn + wn * 64 + nb * 8 + (lane & 3) * 2;
            float* p0 = C + (size_t)r0 * ldc + cc;
            float* p1 = C + (size_t)(r0 + 8) * ldc + cc;
            float2 v0 = make_float2(acc[ma][nb][0], acc[ma][nb][1]);
            float2 v1 = make_float2(acc[ma][nb][2], acc[ma][nb][3]);
            if (ACC) {
                float2 o0 = *(float2*)p0, o1 = *(float2*)p1;
                v0.x += o0.x; v0.y += o0.y;
                v1.x += o1.x; v1.y += o1.y;
            }
            *(float2*)p0 = v0;
            *(float2*)p1 = v1;
        }
    }
}

// ------------------------------------------------------------- conv+silu --
__global__ void conv_silu_kernel(const float* __restrict__ xz,
                                 const float* __restrict__ w,
                                 const float* __restrict__ b,
                                 float* __restrict__ uc)
{
    int idx = blockIdx.x * 256 + threadIdx.x;   // over L*DI
    int l = idx >> 11;
    int d = idx & (DI - 1);
    float s = b[d];
#pragma unroll
    for (int k = 0; k < 4; k++) {
        int tl = l + k - 3;
        if (tl >= 0) s += xz[(size_t)tl * (2*DI) + d] * __ldg(&w[d * 4 + k]);
    }
    uc[idx] = s / (1.f + __expf(-s));
}

// ------------------------------------------------------------------ xproj --
__global__ void __launch_bounds__(256) xproj_kernel(
    const float* __restrict__ uc, const float* __restrict__ W,
    float* __restrict__ xdbl)
{
    __shared__ float sW[96][65];
    __shared__ float sU[8][64];
    const int tid = threadIdx.x;
    const int l0 = blockIdx.x * 8;
    const int tx = tid & 31;
    const int ty = tid >> 5;
    float acc0 = 0.f, acc1 = 0.f, acc2 = 0.f;

    for (int k0 = 0; k0 < DI; k0 += 64) {
        __syncthreads();
#pragma unroll
        for (int i = 0; i < 24; i++) {
            int v = tid + i * 256;
            int ee = v >> 6, rr = v & 63;
            sW[ee][rr] = W[(size_t)ee * DI + k0 + rr];
        }
        {
            int v = tid;
            int ll = v >> 6, rr = v & 63;
            sU[ll][rr] = uc[(size_t)(l0 + ll) * DI + k0 + rr];
            v = tid + 256; ll = v >> 6; rr = v & 63;
            sU[ll][rr] = uc[(size_t)(l0 + ll) * DI + k0 + rr];
        }
        __syncthreads();
#pragma unroll
        for (int r = 0; r < 64; r++) {
            float uv = sU[ty][r];
            acc0 = fmaf(uv, sW[tx][r], acc0);
            acc1 = fmaf(uv, sW[32 + tx][r], acc1);
            acc2 = fmaf(uv, sW[64 + tx][r], acc2);
        }
    }
    size_t base = (size_t)(l0 + ty) * 96;
    xdbl[base + tx]      = acc0;
    xdbl[base + 32 + tx] = acc1;
    xdbl[base + 64 + tx] = acc2;
}

// --------------------------------------------------------------------- dt --
__global__ void __launch_bounds__(256) dt_kernel(
    const float* __restrict__ xdbl, const float* __restrict__ dtw,
    const float* __restrict__ dtb, float* __restrict__ delta)
{
    __shared__ float sW[128][65];
    __shared__ float sR[32][64];
    const int tid = threadIdx.x;
    const int d0 = blockIdx.x * 128;
    const int l0 = blockIdx.y * 32;
#pragma unroll
    for (int i = 0; i < 32; i++) {
        int v = tid + i * 256;
        int dd = v >> 6, rr = v & 63;
        sW[dd][rr] = dtw[(size_t)(d0 + dd) * 64 + rr];
    }
#pragma unroll
    for (int i = 0; i < 8; i++) {
        int v = tid + i * 256;
        int ll = v >> 6, rr = v & 63;
        sR[ll][rr] = xdbl[(size_t)(l0 + ll) * 96 + rr];
    }
    __syncthreads();
    const int tx = tid & 31;
    const int ty = tid >> 5;
    float acc[4][4];
#pragma unroll
    for (int i = 0; i < 4; i++)
#pragma unroll
        for (int j = 0; j < 4; j++) acc[i][j] = 0.f;
#pragma unroll
    for (int r = 0; r < 64; r++) {
        float rv[4], wv[4];
#pragma unroll
        for (int i = 0; i < 4; i++) rv[i] = sR[ty * 4 + i][r];
#pragma unroll
        for (int j = 0; j < 4; j++) wv[j] = sW[j * 32 + tx][r];
#pragma unroll
        for (int i = 0; i < 4; i++)
#pragma unroll
            for (int j = 0; j < 4; j++)
                acc[i][j] = fmaf(rv[i], wv[j], acc[i][j]);
    }
#pragma unroll
    for (int i = 0; i < 4; i++)
#pragma unroll
        for (int j = 0; j < 4; j++) {
            int d = d0 + j * 32 + tx;
            float xv = acc[i][j] + __ldg(&dtb[d]);
            float sp = fmaxf(xv, 0.f) + log1pf(__expf(-fabsf(xv)));
            delta[(size_t)(l0 + ty * 4 + i) * DI + d] = sp;
        }
}

// ------------------------------------------------------------------ A prep --
__global__ void set_flag_kernel() { g_flag = 1; }

__global__ void prepA_kernel(const float* __restrict__ Alog)
{
    int i = blockIdx.x * 256 + threadIdx.x;
    float a = -expf(Alog[i]);
    g_A[i] = a;
    int n = i & 15;
    if (fabsf(a + (float)(n + 1)) > 1e-5f * (float)(n + 1)) g_flag = 0;
}

// --------------------------------------------------- scan pass 1: local ----
// grid (NCH, DI/128), block 128. Local scan per chunk with h_in = 0.
// Writes yloc (incl. u*D), cumulative in-chunk delta S_t, chunk-final h, sumD.
__global__ void __launch_bounds__(128) scan1_kernel(
    const float* __restrict__ delta, const float* __restrict__ xdbl,
    const float* __restrict__ uc, const float* __restrict__ Amat,
    const float* __restrict__ Dsk,
    float* __restrict__ gS, float* __restrict__ gY,
    float* __restrict__ hend, float* __restrict__ chsum)
{
    const int c = blockIdx.x;
    const int d = blockIdx.y * 128 + threadIdx.x;
    __shared__ float sBC[CHT][32];
    for (int i = threadIdx.x; i < CHT * 8; i += 128) {     // float4 units
        int tt = i >> 3, p = (i & 7) << 2;
        *(float4*)&sBC[tt][p] =
            *(const float4*)(xdbl + (size_t)(c * CHT + tt) * 96 + 64 + p);
    }
    __syncthreads();

    float a[NSTATE], h[NSTATE];
#pragma unroll
    for (int n = 0; n < NSTATE; n++) { a[n] = Amat[d * NSTATE + n]; h[n] = 0.f; }
    const float dsk = Dsk[d];
    const int fast = g_flag;
    float S = 0.f;

    const float* dp = delta + (size_t)c * CHT * DI + d;
    const float* up = uc    + (size_t)c * CHT * DI + d;
    float* Sp = gS + (size_t)c * CHT * DI + d;
    float* Yp = gY + (size_t)c * CHT * DI + d;

    for (int tt = 0; tt < CHT; tt++) {
        float dl = dp[(size_t)tt * DI];
        float u  = up[(size_t)tt * DI];
        S += dl;
        Sp[(size_t)tt * DI] = S;
        float du = dl * u;
        float ac0 = 0.f, ac1 = 0.f, ac2 = 0.f, ac3 = 0.f;
        if (fast) {
            float p1 = __expf(-dl);
            float p2 = p1*p1,  p3 = p2*p1,  p4 = p2*p2;
            float p5 = p3*p2,  p6 = p3*p3,  p7 = p4*p3,  p8 = p4*p4;
            float p9 = p5*p4,  p10 = p5*p5, p11 = p6*p5, p12 = p6*p6;
            float p13 = p7*p6, p14 = p7*p7, p15 = p8*p7, p16 = p8*p8;
            float e[16] = {p1,p2,p3,p4,p5,p6,p7,p8,p9,p10,p11,p12,p13,p14,p15,p16};
#pragma unroll
            for (int n = 0; n < NSTATE; n += 4) {
                h[n+0] = fmaf(e[n+0], h[n+0], du * sBC[tt][n+0]);
                ac0 = fmaf(h[n+0], sBC[tt][16+n+0], ac0);
                h[n+1] = fmaf(e[n+1], h[n+1], du * sBC[tt][n+1]);
                ac1 = fmaf(h[n+1], sBC[tt][16+n+1], ac1);
                h[n+2] = fmaf(e[n+2], h[n+2], du * sBC[tt][n+2]);
                ac2 = fmaf(h[n+2], sBC[tt][16+n+2], ac2);
                h[n+3] = fmaf(e[n+3], h[n+3], du * sBC[tt][n+3]);
                ac3 = fmaf(h[n+3], sBC[tt][16+n+3], ac3);
            }
        } else {
#pragma unroll
            for (int n = 0; n < NSTATE; n += 4) {
                float e0 = __expf(dl * a[n+0]);
                float e1 = __expf(dl * a[n+1]);
                float e2 = __expf(dl * a[n+2]);
                float e3 = __expf(dl * a[n+3]);
                h[n+0] = fmaf(e0, h[n+0], du * sBC[tt][n+0]);
                ac0 = fmaf(h[n+0], sBC[tt][16+n+0], ac0);
                h[n+1] = fmaf(e1, h[n+1], du * sBC[tt][n+1]);
                ac1 = fmaf(h[n+1], sBC[tt][16+n+1], ac1);
                h[n+2] = fmaf(e2, h[n+2], du * sBC[tt][n+2]);
                ac2 = fmaf(h[n+2], sBC[tt][16+n+2], ac2);
                h[n+3] = fmaf(e3, h[n+3], du * sBC[tt][n+3]);
                ac3 = fmaf(h[n+3], sBC[tt][16+n+3], ac3);
            }
        }
        float acc = (ac0 + ac1) + (ac2 + ac3);
        Yp[(size_t)tt * DI] = fmaf(u, dsk, acc);
    }

    float* hp = hend + ((size_t)c * DI + d) * NSTATE;
#pragma unroll
    for (int n = 0; n < NSTATE; n += 4)
        *(float4*)(hp + n) = make_float4(h[n], h[n+1], h[n+2], h[n+3]);
    chsum[c * DI + d] = S;
}

// ------------------------------------------- scan pass 2: chunk combine ----
// one thread per (d, n): 16 sequential chunk steps.
__global__ void scan2_kernel(const float* __restrict__ Amat,
                             const float* __restrict__ hend,
                             const float* __restrict__ chsum,
                             float* __restrict__ hin)
{
    int i = blockIdx.x * 256 + threadIdx.x;   // < DI*NSTATE
    int d = i >> 4, n = i & 15;
    const int fast = g_flag;
    float an = fast ? -(float)(n + 1) : Amat[i];
    float h = 0.f;
#pragma unroll
    for (int c = 0; c < NCH; c++) {
        hin[((size_t)c * DI + d) * NSTATE + n] = h;
        float f = __expf(an * chsum[c * DI + d]);
        h = hend[((size_t)c * DI + d) * NSTATE + n] + f * h;
    }
}

// --------------------------------------------- scan pass 3: fixup + gate ---
// grid (NCH, DI/128), block 128.
__global__ void __launch_bounds__(128) scan3_kernel(
    const float* __restrict__ gS, const float* __restrict__ gY,
    const float* __restrict__ xz, const float* __restrict__ xdbl,
    const float* __restrict__ hin, const float* __restrict__ Amat,
    bf16* __restrict__ ygh, bf16* __restrict__ ygl)
{
    const int c = blockIdx.x;
    const int d = blockIdx.y * 128 + threadIdx.x;
    __shared__ float sC[CHT][16];
    for (int i = threadIdx.x; i < CHT * 4; i += 128) {     // float4 units
        int tt = i >> 2, p = (i & 3) << 2;
        *(float4*)&sC[tt][p] =
            *(const float4*)(xdbl + (size_t)(c * CHT + tt) * 96 + 80 + p);
    }
    __syncthreads();

    float hi_[NSTATE], a[NSTATE];
    const float* hp = hin + ((size_t)c * DI + d) * NSTATE;
#pragma unroll
    for (int n = 0; n < NSTATE; n += 4) {
        float4 v = *(const float4*)(hp + n);
        hi_[n] = v.x; hi_[n+1] = v.y; hi_[n+2] = v.z; hi_[n+3] = v.w;
    }
    const int fast = g_flag;
    if (!fast) {
#pragma unroll
        for (int n = 0; n < NSTATE; n++) a[n] = Amat[d * NSTATE + n];
    }

    const float* Sp = gS + (size_t)c * CHT * DI + d;
    const float* Yp = gY + (size_t)c * CHT * DI + d;
    const float* zp = xz + (size_t)c * CHT * (2*DI) + DI + d;
    bf16* oh = ygh + (size_t)c * CHT * DI + d;
    bf16* ol = ygl + (size_t)c * CHT * DI + d;

    for (int tt = 0; tt < CHT; tt++) {
        float S  = Sp[(size_t)tt * DI];
        float yl = Yp[(size_t)tt * DI];
        float zz = zp[(size_t)tt * (2*DI)];
        float acc = 0.f;
        if (fast) {
            float p1 = __expf(-S);
            float p2 = p1*p1,  p3 = p2*p1,  p4 = p2*p2;
            float p5 = p3*p2,  p6 = p3*p3,  p7 = p4*p3,  p8 = p4*p4;
            float p9 = p5*p4,  p10 = p5*p5, p11 = p6*p5, p12 = p6*p6;
            float p13 = p7*p6, p14 = p7*p7, p15 = p8*p7, p16 = p8*p8;
            float e[16] = {p1,p2,p3,p4,p5,p6,p7,p8,p9,p10,p11,p12,p13,p14,p15,p16};
#pragma unroll
            for (int n = 0; n < NSTATE; n++)
                acc = fmaf(e[n] * hi_[n], sC[tt][n], acc);
        } else {
#pragma unroll
            for (int n = 0; n < NSTATE; n++)
                acc = fmaf(__expf(a[n] * S) * hi_[n], sC[tt][n], acc);
        }
        float y = yl + acc;
        float sg = zz / (1.f + __expf(-zz));
        float r = y * sg;
        bf16 hh, ll; split_bf16(r, hh, ll);
        oh[(size_t)tt * DI] = hh;
        ol[(size_t)tt * DI] = ll;
    }
}

// ------------------------------------------------------------------ launch --
extern "C" void kernel_launch(void* const* d_in, const int* in_sizes, int n_in,
                              void* d_out, int out_size)
{
    const float* x      = (const float*)d_in[0];
    const float* norm_w = (const float*)d_in[1];
    const float* in_w   = (const float*)d_in[2];
    const float* conv_w = (const float*)d_in[3];
    const float* conv_b = (const float*)d_in[4];
    const float* xproj_w= (const float*)d_in[5];
    const float* dt_w   = (const float*)d_in[6];
    const float* dt_b   = (const float*)d_in[7];
    const float* A_log  = (const float*)d_in[8];
    const float* D_skip = (const float*)d_in[9];
    const float* out_w  = (const float*)d_in[10];
    float* out = (float*)d_out;

    float *xz, *uc, *xdbl, *delta, *Amat;
    float *S, *yloc, *hend, *hin, *chsum;
    bf16 *xnh, *xnl, *ygh, *ygl, *wih, *wil, *woh, *wol;
    cudaGetSymbolAddress((void**)&xz,    g_xz);
    cudaGetSymbolAddress((void**)&uc,    g_uc);
    cudaGetSymbolAddress((void**)&xdbl,  g_xdbl);
    cudaGetSymbolAddress((void**)&delta, g_delta);
    cudaGetSymbolAddress((void**)&Amat,  g_A);
    cudaGetSymbolAddress((void**)&S,     g_S);
    cudaGetSymbolAddress((void**)&yloc,  g_yloc);
    cudaGetSymbolAddress((void**)&hend,  g_hend);
    cudaGetSymbolAddress((void**)&hin,   g_hin);
    cudaGetSymbolAddress((void**)&chsum, g_chsum);
    cudaGetSymbolAddress((void**)&xnh,   g_xnh);
    cudaGetSymbolAddress((void**)&xnl,   g_xnl);
    cudaGetSymbolAddress((void**)&ygh,   g_ygh);
    cudaGetSymbolAddress((void**)&ygl,   g_ygl);
    cudaGetSymbolAddress((void**)&wih,   g_wih);
    cudaGetSymbolAddress((void**)&wil,   g_wil);
    cudaGetSymbolAddress((void**)&woh,   g_woh);
    cudaGetSymbolAddress((void**)&wol,   g_wol);

    cudaFuncSetAttribute(hmma_gemm<false>,
                         cudaFuncAttributeMaxDynamicSharedMemorySize, HG_SMEM);
    cudaFuncSetAttribute(hmma_gemm<true>,
                         cudaFuncAttributeMaxDynamicSharedMemorySize, HG_SMEM);

    // residual stream init: out = x
    cudaMemcpyAsync(out, x, (size_t)LSEQ * DMODEL * sizeof(float),
                    cudaMemcpyDeviceToDevice, 0);

    for (int lyr = 0; lyr < NL; lyr++) {
        const float* nw  = norm_w  + (size_t)lyr * DMODEL;
        const float* iw  = in_w    + (size_t)lyr * (2*DI) * DMODEL;
        const float* cw  = conv_w  + (size_t)lyr * DI * 4;
        const float* cb  = conv_b  + (size_t)lyr * DI;
        const float* xw  = xproj_w + (size_t)lyr * 96 * DI;
        const float* dw  = dt_w    + (size_t)lyr * DI * DTR;
        const float* db  = dt_b    + (size_t)lyr * DI;
        const float* al  = A_log   + (size_t)lyr * DI * NSTATE;
        const float* ds  = D_skip  + (size_t)lyr * DI;
        const float* ow  = out_w   + (size_t)lyr * DMODEL * DI;

        cvt_kernel<<<(2*DI*DMODEL)/256, 256>>>(iw, wih, wil);
        cvt_kernel<<<(DMODEL*DI)/256, 256>>>(ow, woh, wol);

        rmsnorm_kernel<<<LSEQ, 256>>>(out, nw, xnh, xnl);
        hmma_gemm<false><<<dim3((2*DI)/128, LSEQ/128), 256, HG_SMEM>>>(
            xnh, xnl, wih, wil, xz, 2*DI, DMODEL);
        conv_silu_kernel<<<(LSEQ * DI) / 256, 256>>>(xz, cw, cb, uc);
        xproj_kernel<<<LSEQ / 8, 256>>>(uc, xw, xdbl);
        dt_kernel<<<dim3(DI/128, LSEQ/32), 256>>>(xdbl, dw, db, delta);
        set_flag_kernel<<<1, 1>>>();
        prepA_kernel<<<(DI * NSTATE) / 256, 256>>>(al);

        scan1_kernel<<<dim3(NCH, DI/128), 128>>>(delta, xdbl, uc, Amat, ds,
                                                 S, yloc, hend, chsum);
        scan2_kernel<<<(DI * NSTATE) / 256, 256>>>(Amat, hend, chsum, hin);
        scan3_kernel<<<dim3(NCH, DI/128), 128>>>(S, yloc, xz, xdbl, hin, Amat,
                                                 ygh, ygl);

        hmma_gemm<true><<<dim3(DMODEL/128, LSEQ/128), 256, HG_SMEM>>>(
            ygh, ygl, woh, wol, out, DMODEL, DI);
    }
}